// round 6
// baseline (speedup 1.0000x reference)
#include <cuda_runtime.h>

// Heirachical_Loss — closed-form collapse of the hierarchy matmul.
//
// loss = B - sum_i [ 0.5*S_all + 0.25*S100(t) + 0.125*S10(t) + 0.125*outputs[i,t] ]
//
// Layout: one warp per row; 512-thread blocks (16 warps) so the fused
// last-block epilogue cost (threadfence + atomic + syncthreads per block)
// is amortized over 2x the rows vs 256-thread blocks, and 3 blocks/SM hit
// the 48-warp register-limited occupancy exactly.
// s100 comes from registers already holding the row (100-block = 25
// aligned float4s); only the 10-block needs a 3-float4 L1-hit re-read.
// Final reduce: deterministic fixed-order last-block sum (no float
// atomics; counter auto-wraps so graph replays self-reset).

#define HL_C            1000
#define WARPS_PER_BLOCK 16
#define HL_THREADS      512
#define MAX_BLOCKS      4096   // supports B up to 65536 rows

__device__ float        g_hl_partials[MAX_BLOCKS];
__device__ unsigned int g_hl_count = 0;

__global__ void __launch_bounds__(HL_THREADS, 3) hloss_fused(
    const float* __restrict__ outputs,
    const int*   __restrict__ target,
    float*       __restrict__ out,
    int B)
{
    const int warp = threadIdx.x >> 5;
    const int lane = threadIdx.x & 31;
    const int row  = blockIdx.x * WARPS_PER_BLOCK + warp;

    float part = 0.0f;   // per-lane partial of win(row)
    if (row < B) {
        const int t = target[row];
        const float4* __restrict__ p =
            (const float4*)(outputs + (size_t)row * HL_C);

        const int q0   = ((t / 100) * 100) >> 2;   // 100-block = float4 [q0, q0+25)
        const int lo10 = (t / 10) * 10;
        const int f10  = lo10 >> 2;                // 3 float4s cover the 10-block

        // ---- Front-batch all loads for this row (MLP ~ 9) ----
        float4 v[7];
#pragma unroll
        for (int it = 0; it < 7; ++it)
            v[it] = p[it * 32 + lane];                    // float4 idx 0..223
        float4 vt = make_float4(0.f, 0.f, 0.f, 0.f);
        if (lane < 26) vt = p[224 + lane];                // idx 224..249
        float4 q3 = make_float4(0.f, 0.f, 0.f, 0.f);
        if (lane < 3)  q3 = p[f10 + lane];                // 10-block cover (L1 hit)

        // ---- Row sum + in-register 100-block sum ----
        float s = 0.f, s100 = 0.f;
#pragma unroll
        for (int it = 0; it < 7; ++it) {
            const float sum4 = (v[it].x + v[it].y) + (v[it].z + v[it].w);
            s += sum4;
            if ((unsigned)(it * 32 + lane - q0) < 25u) s100 += sum4;
        }
        {
            const float sum4 = (vt.x + vt.y) + (vt.z + vt.w); // 0 for lane>=26
            s += sum4;
            if ((unsigned)(224 + lane - q0) < 25u) s100 += sum4;
        }

        // ---- 10-block sum + target element (lanes 0-2 hold real data) ----
        float s10 = 0.f, ot = 0.f;
        {
            const float vals[4] = { q3.x, q3.y, q3.z, q3.w };
            const int e0 = (f10 + lane) * 4;
#pragma unroll
            for (int m = 0; m < 4; ++m) {
                const int e = e0 + m;
                if ((unsigned)(e - lo10) < 10u) s10 += vals[m];
                if (e == t)                     ot   = vals[m];
            }
        }

        part = 0.5f * s + 0.25f * s100 + 0.125f * s10 + 0.125f * ot;
    }

    // ---- Warp reduce: part -> win(row), lane-uniform ----
#pragma unroll
    for (int off = 16; off; off >>= 1)
        part += __shfl_xor_sync(0xffffffffu, part, off);

    // ---- Block reduce: one (1 - win) per warp ----
    __shared__ float ws[WARPS_PER_BLOCK];
    __shared__ bool  s_is_last;
    if (lane == 0)
        ws[warp] = (row < B) ? (1.0f - part) : 0.0f;
    __syncthreads();
    if (threadIdx.x == 0) {
        float bsum = 0.f;
#pragma unroll
        for (int w = 0; w < WARPS_PER_BLOCK; ++w) bsum += ws[w];
        g_hl_partials[blockIdx.x] = bsum;
        __threadfence();
        // atomicInc wraps to 0 when old == gridDim.x-1 -> auto-reset per replay.
        unsigned vcnt = atomicInc(&g_hl_count, gridDim.x - 1u);
        s_is_last = (vcnt == gridDim.x - 1u);
    }
    __syncthreads();

    // ---- Last block: deterministic fixed-order final sum ----
    if (s_is_last) {
        __threadfence();
        float a = 0.f;
        for (int i = threadIdx.x; i < (int)gridDim.x; i += HL_THREADS)
            a += g_hl_partials[i];
        __shared__ float sm[HL_THREADS];
        sm[threadIdx.x] = a;
        __syncthreads();
#pragma unroll
        for (int s2 = HL_THREADS / 2; s2; s2 >>= 1) {
            if (threadIdx.x < s2) sm[threadIdx.x] += sm[threadIdx.x + s2];
            __syncthreads();
        }
        if (threadIdx.x == 0) out[0] = sm[0];
    }
}

extern "C" void kernel_launch(void* const* d_in, const int* in_sizes, int n_in,
                              void* d_out, int out_size)
{
    // metadata order: outputs [B*1000] float32, target [B] int32.
    int i_o = 0, i_t = 1;
    if (n_in >= 2 && in_sizes[1] > in_sizes[0]) { i_o = 1; i_t = 0; }

    const float* outputs = (const float*)d_in[i_o];
    const int*   target  = (const int*)d_in[i_t];
    const int B = in_sizes[i_t];

    int nblocks = (B + WARPS_PER_BLOCK - 1) / WARPS_PER_BLOCK;  // 2048 for B=32768
    if (nblocks > MAX_BLOCKS) nblocks = MAX_BLOCKS;

    hloss_fused<<<nblocks, HL_THREADS>>>(outputs, target, (float*)d_out, B);
}

// round 8
// speedup vs baseline: 1.1393x; 1.1393x over previous
#include <cuda_runtime.h>

// Heirachical_Loss — closed-form collapse + split reduction.
//
//   loss = B - [ 0.5 * sum(ALL outputs)                                  (flat scan, 131 MB)
//              + sum_i ( 0.25*S100_i + 0.125*S10_i + 0.125*out[i,t_i] ) ] (25-lane gather, 13 MB)
//
// Flat scan removes all per-row overhead (no tails, no per-row shuffle
// chains, no target dependency) from the bandwidth-dominant pass.
// Single-wave persistent grid: 888 blocks = 148 SMs x 6 blocks of 256 thr.
// Deterministic fused last-block reduce (fixed order, no float atomics;
// counter auto-wraps so graph replays self-reset).

#define HL_C        1000
#define HL_V4       (HL_C / 4)      // 250 float4 per row
#define HL_THREADS  256
#define HL_WPB      8               // warps per block
#define HL_GRID     888             // 148 * 6, single wave at 6 blocks/SM
#define MAX_BLOCKS  1024

__device__ float        g_hl_partials[MAX_BLOCKS];
__device__ unsigned int g_hl_count = 0;

__global__ void __launch_bounds__(HL_THREADS, 6) hloss_fused(
    const float* __restrict__ outputs,
    const int*   __restrict__ target,
    float*       __restrict__ out,
    int B)
{
    const int tid  = threadIdx.x;
    const int warp = tid >> 5;
    const int lane = tid & 31;
    const float4* __restrict__ p4 = (const float4*)outputs;

    float acc = 0.0f;   // per-lane accumulation of win contributions

    // ---- Phase 2: hierarchy terms (target's 100-block), grid-strided rows ----
    {
        const int warps_total = gridDim.x * HL_WPB;
        for (int row = blockIdx.x * HL_WPB + warp; row < B; row += warps_total) {
            const int t     = target[row];
            const int lo100 = (t / 100) * 100;
            const int lo10  = (t / 10)  * 10;
            if (lane < 25) {
                const float4 q = p4[(long)row * HL_V4 + (lo100 >> 2) + lane];
                const float  s100 = (q.x + q.y) + (q.z + q.w);
                const float  vals[4] = { q.x, q.y, q.z, q.w };
                float s10 = 0.f, ot = 0.f;
                const int e0 = lo100 + lane * 4;
#pragma unroll
                for (int m = 0; m < 4; ++m) {
                    const int e = e0 + m;
                    if ((unsigned)(e - lo10) < 10u) s10 += vals[m];
                    if (e == t)                     ot   = vals[m];
                }
                acc += 0.25f * s100 + 0.125f * s10 + 0.125f * ot;
            }
        }
    }

    // ---- Phase 1: flat sum of the whole matrix (0.5 weight), grid-strided ----
    {
        const long NV4    = (long)B * HL_V4;
        const long stride = (long)gridDim.x * HL_THREADS;
        long i = (long)blockIdx.x * HL_THREADS + tid;
        float s = 0.0f;
        for (; i + 3 * stride < NV4; i += 4 * stride) {
            const float4 a = p4[i];
            const float4 b = p4[i +     stride];
            const float4 c = p4[i + 2 * stride];
            const float4 d = p4[i + 3 * stride];
            s += ((a.x + a.y) + (a.z + a.w)) + ((b.x + b.y) + (b.z + b.w))
               + ((c.x + c.y) + (c.z + c.w)) + ((d.x + d.y) + (d.z + d.w));
        }
        for (; i < NV4; i += stride) {
            const float4 a = p4[i];
            s += (a.x + a.y) + (a.z + a.w);
        }
        acc += 0.5f * s;
    }

    // ---- One warp reduce per kernel ----
#pragma unroll
    for (int off = 16; off; off >>= 1)
        acc += __shfl_xor_sync(0xffffffffu, acc, off);

    // ---- Block partial ----
    __shared__ float ws[HL_WPB];
    __shared__ bool  s_is_last;
    if (lane == 0) ws[warp] = acc;
    __syncthreads();
    if (tid == 0) {
        float bsum = 0.f;
#pragma unroll
        for (int w = 0; w < HL_WPB; ++w) bsum += ws[w];
        g_hl_partials[blockIdx.x] = bsum;
        __threadfence();
        // atomicInc wraps to 0 when old == gridDim.x-1 -> auto-reset per replay.
        unsigned vcnt = atomicInc(&g_hl_count, gridDim.x - 1u);
        s_is_last = (vcnt == gridDim.x - 1u);
    }
    __syncthreads();

    // ---- Last block: deterministic fixed-order final sum ----
    if (s_is_last) {
        __threadfence();
        float a = 0.f;
        for (int i = tid; i < (int)gridDim.x; i += HL_THREADS)
            a += g_hl_partials[i];
        __shared__ float sm[HL_THREADS];
        sm[tid] = a;
        __syncthreads();
#pragma unroll
        for (int s2 = HL_THREADS / 2; s2; s2 >>= 1) {
            if (tid < s2) sm[tid] += sm[tid + s2];
            __syncthreads();
        }
        if (tid == 0) out[0] = (float)B - sm[0];
    }
}

extern "C" void kernel_launch(void* const* d_in, const int* in_sizes, int n_in,
                              void* d_out, int out_size)
{
    // metadata order: outputs [B*1000] float32, target [B] int32.
    int i_o = 0, i_t = 1;
    if (n_in >= 2 && in_sizes[1] > in_sizes[0]) { i_o = 1; i_t = 0; }

    const float* outputs = (const float*)d_in[i_o];
    const int*   target  = (const int*)d_in[i_t];
    const int B = in_sizes[i_t];

    int nblocks = HL_GRID;
    // For tiny B don't launch more blocks than rows (keeps epilogue sane).
    int max_useful = (B + HL_WPB - 1) / HL_WPB;
    if (nblocks > max_useful) nblocks = max_useful;
    if (nblocks < 1) nblocks = 1;

    hloss_fused<<<nblocks, HL_THREADS>>>(outputs, target, (float*)d_out, B);
}

// round 12
// speedup vs baseline: 1.2267x; 1.0767x over previous
#include <cuda_runtime.h>

// Heirachical_Loss — closed-form collapse of the hierarchy matmul.
//
// loss = B - sum_i [ 0.5*S_all + 0.25*S100(t) + 0.125*S10(t) + 0.125*outputs[i,t] ]
//
// Main kernel: R2 structure verbatim (best measured: 23.6us, ~6.1 TB/s).
// Reduce kernel: rebuilt — 1024 threads, one float4 each, single memory
// round-trip + deterministic shared-memory tree (was 4.7us, now <1us).

#define HL_C 1000
#define ROWS_PER_BLOCK 8
#define HL_THREADS 256
#define MAX_BLOCKS 8192

__device__ float g_hl_partials[MAX_BLOCKS];   // 16B-aligned (global array)

__global__ void __launch_bounds__(HL_THREADS) hloss_main(
    const float* __restrict__ outputs,
    const int*   __restrict__ target,
    int B)
{
    const int warp = threadIdx.x >> 5;
    const int lane = threadIdx.x & 31;
    const int row  = blockIdx.x * ROWS_PER_BLOCK + warp;

    float win = 0.0f;
    if (row < B) {
        const int t = target[row];
        const float4* __restrict__ p =
            (const float4*)(outputs + (size_t)row * HL_C);

        // ---- Phase 1: full-row sum (250 float4 per row, front-batched loads) ----
        float4 v[7];
#pragma unroll
        for (int it = 0; it < 7; ++it)
            v[it] = p[it * 32 + lane];            // covers float4 idx 0..223
        float4 vt = make_float4(0.f, 0.f, 0.f, 0.f);
        if (lane < 26)
            vt = p[224 + lane];                   // covers idx 224..249

        float s = (vt.x + vt.y) + (vt.z + vt.w);
#pragma unroll
        for (int it = 0; it < 7; ++it)
            s += (v[it].x + v[it].y) + (v[it].z + v[it].w);

        // ---- Phase 2: special 100-block (L1 hit — just loaded) ----
        const int lo100 = (t / 100) * 100;        // 4-aligned
        const int lo10  = (t / 10)  * 10;
        float s100 = 0.f, s10 = 0.f, ot = 0.f;
        if (lane < 25) {
            float4 q = p[(lo100 >> 2) + lane];
            const int e0 = lo100 + lane * 4;
            float vals[4] = { q.x, q.y, q.z, q.w };
#pragma unroll
            for (int m = 0; m < 4; ++m) {
                const int e = e0 + m;
                const float vv = vals[m];
                s100 += vv;
                if ((unsigned)(e - lo10) < 10u) s10 += vv;
                if (e == t)                     ot  = vv;
            }
        }

        float part = 0.5f * s + 0.25f * s100 + 0.125f * s10 + 0.125f * ot;
#pragma unroll
        for (int off = 16; off; off >>= 1)
            part += __shfl_xor_sync(0xffffffffu, part, off);
        win = part;
    }

    // ---- Block reduce: one win per warp -> per-block partial of (1 - win) ----
    __shared__ float ws[ROWS_PER_BLOCK];
    if (lane == 0)
        ws[warp] = (row < B) ? (1.0f - win) : 0.0f;
    __syncthreads();
    if (threadIdx.x == 0) {
        float acc = 0.f;
#pragma unroll
        for (int w = 0; w < ROWS_PER_BLOCK; ++w) acc += ws[w];
        g_hl_partials[blockIdx.x] = acc;
    }
}

// Fast final reduce: n <= MAX_BLOCKS partials. 1024 threads, each loads one
// float4 (4096 floats max) in a single parallel round-trip, then a
// deterministic fixed-order shared-memory tree.
__global__ void __launch_bounds__(1024) hloss_reduce(float* __restrict__ out, int n)
{
    __shared__ float sm[1024];
    const int tid = threadIdx.x;

    const int n4 = n >> 2;                        // number of full float4s
    float a = 0.f;
    if (tid < n4) {
        const float4 q = ((const float4*)g_hl_partials)[tid];
        a = (q.x + q.y) + (q.z + q.w);
    }
    // ragged tail (n not multiple of 4) handled by thread n4
    if (tid == n4) {
        for (int i = n4 << 2; i < n; ++i)
            a += g_hl_partials[i];
    }
    sm[tid] = a;
    __syncthreads();
#pragma unroll
    for (int s = 512; s; s >>= 1) {
        if (tid < s) sm[tid] += sm[tid + s];
        __syncthreads();
    }
    if (tid == 0) out[0] = sm[0];
}

extern "C" void kernel_launch(void* const* d_in, const int* in_sizes, int n_in,
                              void* d_out, int out_size)
{
    // metadata order: outputs [B*1000] float32, target [B] int32.
    int i_o = 0, i_t = 1;
    if (n_in >= 2 && in_sizes[1] > in_sizes[0]) { i_o = 1; i_t = 0; }

    const float* outputs = (const float*)d_in[i_o];
    const int*   target  = (const int*)d_in[i_t];
    const int B = in_sizes[i_t];

    int nblocks = (B + ROWS_PER_BLOCK - 1) / ROWS_PER_BLOCK;  // 4096 for B=32768
    if (nblocks > MAX_BLOCKS) nblocks = MAX_BLOCKS;

    hloss_main<<<nblocks, HL_THREADS>>>(outputs, target, B);
    hloss_reduce<<<1, 1024>>>((float*)d_out, nblocks);
}